// round 14
// baseline (speedup 1.0000x reference)
#include <cuda_runtime.h>
#include <math_constants.h>

// Hausdorff loss: x,y (8, 4096, 3) fp32 -> scalar, ONE kernel launch.
// FUSED BIDIRECTIONAL: one distance matrix serves both directions.
//   u   = |x|^2 - 2 x.y            (3 FFMA, chain seeded with |x|^2)
//   row (x-side NN): min_j (u + w_j)        -> 1 FADD + 1 FMNMX per pair
//   col (y-side NN): (min_i u) + w_j        -> 1 FMNMX per pair (add deferred)
// Half the pairs of the two-direction scan; 4 fma-pipe ops/pair.
//
// Decomposition: 8 batches x 74 target-chunks = 592 CTAs = 4/SM (148*4).
// CTA stages <=56 targets (sentinel-padded) in smem, scans all 4096 queries
// (4/thread, 4 passes). Col mins: c[8] register accumulators per 8-target
// sub-block, flushed via shfl-min to warp-private smem cells (complete
// locally). Row mins: complement-bits atomicMax slab (identity 0 -> no init
// kernel); per-slab last-done CTA (of 74) reduces + restores; global
// last-done emits the scalar and resets all state (graph-replay safe).

#define NB 8
#define V  4096
#define TC 74                         // 8*74 = 592 CTAs = 148*4
#define THREADS 256
#define QPT 4
#define NPASS (V / (QPT * THREADS))   // 4
#define NTP 56                        // padded targets per chunk (= 7*8)
#define NSB (NTP / 8)                 // 7 sub-blocks
#define NWARP (THREADS / 32)

__device__ unsigned g_comp[NB * V];   // zero-init == identity for max(~bits)
__device__ unsigned g_max[NB];
__device__ unsigned g_slab_done[NB];
__device__ unsigned g_done;

__global__ void __launch_bounds__(THREADS, 4)
hd_main_kernel(const float* __restrict__ X, const float* __restrict__ Y,
               float* __restrict__ out) {
    __shared__ float4 sT[NTP];
    __shared__ float scol[NTP][NWARP];   // per-warp col-min of u (can be <0)
    __shared__ float wmax[NWARP];
    __shared__ int s_role;

    const int tc = blockIdx.x;           // 0..73
    const int b  = blockIdx.y;
    const float* __restrict__ Xb = X + (size_t)b * V * 3;
    const float* __restrict__ Yb = Y + (size_t)b * V * 3;
    unsigned* __restrict__ slab = g_comp + (size_t)b * V;   // x-side NN^2

    const int t0 = (tc * V) / TC;
    const int nt = ((tc + 1) * V) / TC - t0;   // 55 or 56
    const int tid = threadIdx.x;
    const int wid = tid >> 5;
    const int lid = tid & 31;

    // Stage targets (y-points): (x, y, z, |t|^2); pad with (0,0,0,+INF).
    // Sentinel: row sees u + INF = INF (ignored); col guarded at the fold.
    if (tid < NTP) {
        float4 v = make_float4(0.0f, 0.0f, 0.0f, CUDART_INF_F);
        if (tid < nt) {
            const int g = t0 + tid;
            const float tx = Yb[g * 3 + 0];
            const float ty = Yb[g * 3 + 1];
            const float tz = Yb[g * 3 + 2];
            v = make_float4(tx, ty, tz, tx * tx + ty * ty + tz * tz);
        }
        sT[tid] = v;
    }
    for (int i = tid; i < NTP * NWARP; i += THREADS)
        (&scol[0][0])[i] = CUDART_INF_F;
    __syncthreads();

    #pragma unroll 1
    for (int p = 0; p < NPASS; p++) {
        const int qb = p * (QPT * THREADS) + tid;

        float ax[QPT], ay[QPT], az[QPT], x2[QPT], m[QPT];
        #pragma unroll
        for (int k = 0; k < QPT; k++) {
            const int q = qb + k * THREADS;
            const float qx = Xb[q * 3 + 0];
            const float qy = Xb[q * 3 + 1];
            const float qz = Xb[q * 3 + 2];
            ax[k] = -2.0f * qx; ay[k] = -2.0f * qy; az[k] = -2.0f * qz;
            x2[k] = qx * qx + qy * qy + qz * qz;
            m[k]  = CUDART_INF_F;
        }

        #pragma unroll 1
        for (int sb = 0; sb < NSB; sb++) {
            float c[8];
            #pragma unroll
            for (int j = 0; j < 8; j++) c[j] = CUDART_INF_F;

            #pragma unroll
            for (int j = 0; j < 8; j++) {
                const float4 t = sT[sb * 8 + j];   // broadcast LDS.128
                #pragma unroll
                for (int k = 0; k < QPT; k++) {
                    // u = |x|^2 - 2 x.y  (chain seeded with |x|^2)
                    const float u = fmaf(ax[k], t.x,
                                    fmaf(ay[k], t.y,
                                    fmaf(az[k], t.z, x2[k])));
                    m[k] = fminf(m[k], u + t.w);   // row: d^2 = u + |y|^2
                    c[j] = fminf(c[j], u);         // col: add w later
                }
            }

            // Flush col sub-block: warp float-min, lane0 -> private cell.
            #pragma unroll
            for (int j = 0; j < 8; j++) {
                float v = c[j];
                #pragma unroll
                for (int off = 16; off > 0; off >>= 1)
                    v = fminf(v, __shfl_xor_sync(0xffffffffu, v, off));
                if (lid == 0) {
                    const int tj = sb * 8 + j;
                    scol[tj][wid] = fminf(scol[tj][wid], v);
                }
            }
        }

        #pragma unroll
        for (int k = 0; k < QPT; k++) {
            const float s = fmaxf(m[k], 0.0f);     // clamp (monotone, safe)
            // min over chunks == ~(max over chunks of ~bits); identity 0.
            atomicMax(&slab[qb + k * THREADS], ~__float_as_uint(s));
        }
    }

    // ---- y-side: column results are COMPLETE in this CTA ----
    __syncthreads();
    float my = 0.0f;
    if (tid < nt) {
        float u = scol[tid][0];
        #pragma unroll
        for (int w = 1; w < NWARP; w++) u = fminf(u, scol[tid][w]);
        my = fmaxf(u + sT[tid].w, 0.0f);           // NN^2 for target t0+tid
    }
    #pragma unroll
    for (int off = 16; off > 0; off >>= 1)
        my = fmaxf(my, __shfl_xor_sync(0xffffffffu, my, off));
    if (lid == 0) wmax[wid] = my;
    __syncthreads();
    if (tid == 0) {
        float mx = wmax[0];
        #pragma unroll
        for (int w = 1; w < NWARP; w++) mx = fmaxf(mx, wmax[w]);
        atomicMax(&g_max[b], __float_as_uint(mx));  // nonneg bits
    }

    // ---- per-slab last-done CTA (of 74) reduces the x-side slab ----
    __threadfence();
    __syncthreads();
    if (tid == 0)
        s_role = (atomicAdd(&g_slab_done[b], 1u) == TC - 1);
    __syncthreads();
    if (!s_role) return;

    __threadfence();   // acquire: all 74 CTAs' atomics visible

    float mm = 0.0f;
    {
        uint4* __restrict__ slab4 = reinterpret_cast<uint4*>(slab);
        #pragma unroll
        for (int i = tid; i < V / 4; i += THREADS) {
            const uint4 w = slab4[i];
            mm = fmaxf(mm, __uint_as_float(~w.x));
            mm = fmaxf(mm, __uint_as_float(~w.y));
            mm = fmaxf(mm, __uint_as_float(~w.z));
            mm = fmaxf(mm, __uint_as_float(~w.w));
            slab4[i] = make_uint4(0u, 0u, 0u, 0u);   // restore identity
        }
    }
    #pragma unroll
    for (int off = 16; off > 0; off >>= 1)
        mm = fmaxf(mm, __shfl_xor_sync(0xffffffffu, mm, off));
    if (lid == 0) wmax[wid] = mm;
    __syncthreads();

    if (tid == 0) {
        float mx = wmax[0];
        #pragma unroll
        for (int w = 1; w < NWARP; w++) mx = fmaxf(mx, wmax[w]);
        atomicMax(&g_max[b], __float_as_uint(mx));
        g_slab_done[b] = 0u;                   // restore (all 74 arrived)

        __threadfence();
        if (atomicAdd(&g_done, 1u) == NB - 1) {   // global last: finalize
            __threadfence();
            float s = 0.0f;
            #pragma unroll
            for (int i = 0; i < NB; i++) {
                s += sqrtf(__uint_as_float(g_max[i]));
                g_max[i] = 0u;                 // restore
            }
            out[0] = s * (1.0f / (float)NB);   // LOSS_WEIGHT = 1.0
            g_done = 0u;                       // restore
        }
    }
}

extern "C" void kernel_launch(void* const* d_in, const int* in_sizes, int n_in,
                              void* d_out, int out_size) {
    const float* x = (const float*)d_in[0];
    const float* y = (const float*)d_in[1];
    float* out = (float*)d_out;

    dim3 grid(TC, NB);
    hd_main_kernel<<<grid, THREADS>>>(x, y, out);
}